// round 3
// baseline (speedup 1.0000x reference)
#include <cuda_runtime.h>
#include <math.h>

#define BB 2
#define SS 2048
#define DD 1024
#define HH 16
#define HW 64
#define MM (BB*SS)   // 4096

// ---------------- scratch (no cudaMalloc allowed): 48 MB total --------------
__device__ float g_Q[(size_t)MM * DD];
__device__ float g_K[(size_t)MM * DD];
__device__ float g_V[(size_t)MM * DD];

// ---------------- fast exp on the FFMA pipe (avoid MUFU bottleneck) ---------
__device__ __forceinline__ float fexp(float x) {
    float y = fmaxf(x * 1.4426950408889634f, -126.0f);
    float n = rintf(y);
    float f = y - n;
    // 2^f Taylor (ln2 powers), f in [-0.5, 0.5], abs err ~1e-7
    float p =              1.5403530393381606e-4f;
    p = fmaf(p, f, 1.3333558146428443e-3f);
    p = fmaf(p, f, 9.6181291076284772e-3f);
    p = fmaf(p, f, 5.5504108664821580e-2f);
    p = fmaf(p, f, 2.4022650695910071e-1f);
    p = fmaf(p, f, 6.9314718055994531e-1f);
    p = fmaf(p, f, 1.0f);
    int e = (((int)n) + 127) << 23;
    return p * __int_as_float(e);
}

// ---------------- K1: C = X @ W^T + b  (W row-major [N,K]) -------------------
// 128x128 block tile, BK=16, 256 threads, 8x8 microtile
__global__ void __launch_bounds__(256)
gemm_xwt_bias(const float* __restrict__ A, const float* __restrict__ Wt,
              const float* __restrict__ bias, int which) {
    float* C = (which == 0) ? g_Q : (which == 1) ? g_K : g_V;
    __shared__ float As[16][132];
    __shared__ float Bs[16][132];
    const int tid = threadIdx.x;
    const int m0 = blockIdx.y * 128;
    const int n0 = blockIdx.x * 128;
    const int ty = tid >> 4;
    const int tx = tid & 15;
    float acc[8][8];
#pragma unroll
    for (int i = 0; i < 8; i++)
#pragma unroll
        for (int j = 0; j < 8; j++) acc[i][j] = 0.f;

    for (int k0 = 0; k0 < DD; k0 += 16) {
#pragma unroll
        for (int r = 0; r < 2; r++) {
            int idx = tid + r * 256;
            int row = idx >> 2;
            int c4  = idx & 3;
            float4 va = *(const float4*)(A  + (size_t)(m0 + row) * DD + k0 + c4 * 4);
            As[c4*4+0][row] = va.x; As[c4*4+1][row] = va.y;
            As[c4*4+2][row] = va.z; As[c4*4+3][row] = va.w;
            float4 vb = *(const float4*)(Wt + (size_t)(n0 + row) * DD + k0 + c4 * 4);
            Bs[c4*4+0][row] = vb.x; Bs[c4*4+1][row] = vb.y;
            Bs[c4*4+2][row] = vb.z; Bs[c4*4+3][row] = vb.w;
        }
        __syncthreads();
#pragma unroll
        for (int k = 0; k < 16; k++) {
            float a[8], b[8];
#pragma unroll
            for (int i = 0; i < 4; i++) {
                a[i]     = As[k][ty*4 + i];
                a[4 + i] = As[k][64 + ty*4 + i];
                b[i]     = Bs[k][tx*4 + i];
                b[4 + i] = Bs[k][64 + tx*4 + i];
            }
#pragma unroll
            for (int i = 0; i < 8; i++)
#pragma unroll
                for (int j = 0; j < 8; j++) acc[i][j] = fmaf(a[i], b[j], acc[i][j]);
        }
        __syncthreads();
    }
#pragma unroll
    for (int i = 0; i < 8; i++) {
        int r  = (i < 4) ? (ty*4 + i) : (64 + ty*4 + (i - 4));
        int gm = m0 + r;
#pragma unroll
        for (int cj = 0; cj < 2; cj++) {
            int c = n0 + cj * 64 + tx * 4;
            float4 bv = *(const float4*)(bias + c);
            float4 o;
            o.x = acc[i][cj*4+0] + bv.x;
            o.y = acc[i][cj*4+1] + bv.y;
            o.z = acc[i][cj*4+2] + bv.z;
            o.w = acc[i][cj*4+3] + bv.w;
            *(float4*)(C + (size_t)gm * DD + c) = o;
        }
    }
}

// ---------------- K2: fused attention (scores + double softmax + PV) --------
// One CTA = 64 q rows of one (b,h). 256 threads, 4x4 microtiles.
// smem: Qs[w][q], Ks[w][k], Ts[q][k], Vs[k][w], each 64x68 fp32.
#define TSTR 68
#define TILE_F (64 * TSTR)

__global__ void __launch_bounds__(256)
attn_fused(float* __restrict__ out) {
    extern __shared__ float sm[];
    float* Qs = sm;
    float* Ks = sm + TILE_F;
    float* Ts = sm + 2 * TILE_F;
    float* Vs = sm + 3 * TILE_F;

    const int bh = blockIdx.z;
    const int b  = bh >> 4, h = bh & 15;
    const int q0 = blockIdx.x * 64;
    const int tid = threadIdx.x;
    const int ty = tid >> 4, tx = tid & 15;

    // load Q tile transposed: Qs[w][q]
#pragma unroll
    for (int r = 0; r < 4; r++) {
        int idx = tid + r * 256;
        int row = idx >> 4;     // q (0..63)
        int c4  = idx & 15;     // w/4
        float4 v = *(const float4*)(g_Q + (size_t)(b*SS + q0 + row) * DD + h*HW + c4*4);
        Qs[(c4*4+0)*TSTR + row] = v.x; Qs[(c4*4+1)*TSTR + row] = v.y;
        Qs[(c4*4+2)*TSTR + row] = v.z; Qs[(c4*4+3)*TSTR + row] = v.w;
    }

    float m[4], z[4];
#pragma unroll
    for (int i = 0; i < 4; i++) { m[i] = -1e30f; z[i] = 0.f; }

    // ---------------- pass 1: online (max, Z1) ------------------------------
    for (int n0 = 0; n0 < SS; n0 += 64) {
#pragma unroll
        for (int r = 0; r < 4; r++) {
            int idx = tid + r * 256;
            int row = idx >> 4;
            int c4  = idx & 15;
            float4 v = *(const float4*)(g_K + (size_t)(b*SS + n0 + row) * DD + h*HW + c4*4);
            Ks[(c4*4+0)*TSTR + row] = v.x; Ks[(c4*4+1)*TSTR + row] = v.y;
            Ks[(c4*4+2)*TSTR + row] = v.z; Ks[(c4*4+3)*TSTR + row] = v.w;
        }
        __syncthreads();

        float s[4][4];
#pragma unroll
        for (int i = 0; i < 4; i++)
#pragma unroll
            for (int j = 0; j < 4; j++) s[i][j] = 0.f;
#pragma unroll
        for (int w = 0; w < 64; w++) {
            float4 a4 = *(const float4*)(Qs + w*TSTR + ty*4);
            float4 b4 = *(const float4*)(Ks + w*TSTR + tx*4);
            float a[4] = {a4.x, a4.y, a4.z, a4.w};
            float bb[4] = {b4.x, b4.y, b4.z, b4.w};
#pragma unroll
            for (int i = 0; i < 4; i++)
#pragma unroll
                for (int j = 0; j < 4; j++) s[i][j] = fmaf(a[i], bb[j], s[i][j]);
        }
#pragma unroll
        for (int i = 0; i < 4; i++) {
#pragma unroll
            for (int j = 0; j < 4; j++) s[i][j] *= 0.125f;
            float tmax = fmaxf(fmaxf(s[i][0], s[i][1]), fmaxf(s[i][2], s[i][3]));
            float nm = fmaxf(m[i], tmax);
            float zs = (fexp(s[i][0]-nm) + fexp(s[i][1]-nm))
                     + (fexp(s[i][2]-nm) + fexp(s[i][3]-nm));
            z[i] = z[i] * fexp(m[i] - nm) + zs;
            m[i] = nm;
        }
        __syncthreads();
    }

    // merge (m,z) across the 16 lanes sharing a row group
#pragma unroll
    for (int o = 8; o; o >>= 1) {
#pragma unroll
        for (int i = 0; i < 4; i++) {
            float om = __shfl_xor_sync(0xffffffffu, m[i], o);
            float oz = __shfl_xor_sync(0xffffffffu, z[i], o);
            float nm = fmaxf(m[i], om);
            z[i] = z[i] * fexp(m[i] - nm) + oz * fexp(om - nm);
            m[i] = nm;
        }
    }
    float invZ1[4];
#pragma unroll
    for (int i = 0; i < 4; i++) invZ1[i] = 1.0f / z[i];

    // ---------------- pass 2: t = exp(exp(s-m)/Z1); acc += t @ V ------------
    float acc[4][4];
    float z2[4];
#pragma unroll
    for (int i = 0; i < 4; i++) {
        z2[i] = 0.f;
#pragma unroll
        for (int j = 0; j < 4; j++) acc[i][j] = 0.f;
    }

    for (int n0 = 0; n0 < SS; n0 += 64) {
#pragma unroll
        for (int r = 0; r < 4; r++) {
            int idx = tid + r * 256;
            int row = idx >> 4;
            int c4  = idx & 15;
            float4 vk = *(const float4*)(g_K + (size_t)(b*SS + n0 + row) * DD + h*HW + c4*4);
            Ks[(c4*4+0)*TSTR + row] = vk.x; Ks[(c4*4+1)*TSTR + row] = vk.y;
            Ks[(c4*4+2)*TSTR + row] = vk.z; Ks[(c4*4+3)*TSTR + row] = vk.w;
            float4 vv = *(const float4*)(g_V + (size_t)(b*SS + n0 + row) * DD + h*HW + c4*4);
            *(float4*)(Vs + row*TSTR + c4*4) = vv;
        }
        __syncthreads();

        float s[4][4];
#pragma unroll
        for (int i = 0; i < 4; i++)
#pragma unroll
            for (int j = 0; j < 4; j++) s[i][j] = 0.f;
#pragma unroll
        for (int w = 0; w < 64; w++) {
            float4 a4 = *(const float4*)(Qs + w*TSTR + ty*4);
            float4 b4 = *(const float4*)(Ks + w*TSTR + tx*4);
            float a[4] = {a4.x, a4.y, a4.z, a4.w};
            float bb[4] = {b4.x, b4.y, b4.z, b4.w};
#pragma unroll
            for (int i = 0; i < 4; i++)
#pragma unroll
                for (int j = 0; j < 4; j++) s[i][j] = fmaf(a[i], bb[j], s[i][j]);
        }
#pragma unroll
        for (int i = 0; i < 4; i++) {
#pragma unroll
            for (int j = 0; j < 4; j++) {
                float p = fexp(s[i][j] * 0.125f - m[i]);  // first softmax numerator
                float t = fexp(p * invZ1[i]);             // second softmax numerator
                z2[i] += t;
                s[i][j] = t;
            }
            *(float4*)(Ts + (ty*4 + i)*TSTR + tx*4) =
                make_float4(s[i][0], s[i][1], s[i][2], s[i][3]);
        }
        __syncthreads();

#pragma unroll
        for (int k = 0; k < 64; k++) {
            float4 vv = *(const float4*)(Vs + k*TSTR + tx*4);
            float ta[4];
#pragma unroll
            for (int i = 0; i < 4; i++) ta[i] = Ts[(ty*4 + i)*TSTR + k];
#pragma unroll
            for (int i = 0; i < 4; i++) {
                acc[i][0] = fmaf(ta[i], vv.x, acc[i][0]);
                acc[i][1] = fmaf(ta[i], vv.y, acc[i][1]);
                acc[i][2] = fmaf(ta[i], vv.z, acc[i][2]);
                acc[i][3] = fmaf(ta[i], vv.w, acc[i][3]);
            }
        }
        __syncthreads();
    }

    // reduce Z2 across the 16-lane row group, then scale + write out
#pragma unroll
    for (int o = 8; o; o >>= 1)
#pragma unroll
        for (int i = 0; i < 4; i++) z2[i] += __shfl_xor_sync(0xffffffffu, z2[i], o);

#pragma unroll
    for (int i = 0; i < 4; i++) {
        float r = 1.0f / z2[i];
        float4 o;
        o.x = acc[i][0] * r; o.y = acc[i][1] * r;
        o.z = acc[i][2] * r; o.w = acc[i][3] * r;
        *(float4*)(out + (size_t)(b*SS + q0 + ty*4 + i) * DD + h*HW + tx*4) = o;
    }
}

// ---------------- launch -----------------------------------------------------
extern "C" void kernel_launch(void* const* d_in, const int* in_sizes, int n_in,
                              void* d_out, int out_size) {
    const float* x  = (const float*)d_in[0];
    const float* Wq = (const float*)d_in[1];
    const float* bq = (const float*)d_in[2];
    const float* Wk = (const float*)d_in[3];
    const float* bk = (const float*)d_in[4];
    const float* Wv = (const float*)d_in[5];
    const float* bv = (const float*)d_in[6];
    float* out = (float*)d_out;

    dim3 gproj(DD / 128, MM / 128);             // (8, 32)
    gemm_xwt_bias<<<gproj, 256>>>(x, Wq, bq, 0);
    gemm_xwt_bias<<<gproj, 256>>>(x, Wk, bk, 1);
    gemm_xwt_bias<<<gproj, 256>>>(x, Wv, bv, 2);

    const int smem_bytes = 4 * TILE_F * sizeof(float);  // 69632
    cudaFuncSetAttribute(attn_fused, cudaFuncAttributeMaxDynamicSharedMemorySize,
                         smem_bytes);
    dim3 gattn(SS / 64, 1, BB * HH);            // (32, 1, 32)
    attn_fused<<<gattn, 256, smem_bytes>>>(out);
}

// round 5
// speedup vs baseline: 1.4749x; 1.4749x over previous
#include <cuda_runtime.h>
#include <cstdint>
#include <math.h>

#define BB 2
#define SS 2048
#define DD 1024
#define HH 16
#define HW 64
#define MM (BB*SS)   // 4096

// ---------------- scratch (no cudaMalloc allowed) ---------------------------
__device__ float g_Q[(size_t)MM * DD];                 // 16 MB
__device__ float g_K[(size_t)MM * DD];                 // 16 MB
__device__ float g_V[(size_t)MM * DD];                 // 16 MB
__device__ float g_S[(size_t)BB * HH * SS * SS];       // 512 MB  (e^s cache)
__device__ float g_Z[(size_t)BB * HH * SS];            // row sums Z1

// ---------------- tf32 helpers (non-arch-specific PTX only!) ----------------
__device__ __forceinline__ uint32_t f2tf32(float x) {
    uint32_t u; asm("cvt.rna.tf32.f32 %0, %1;" : "=r"(u) : "f"(x)); return u;
}

__device__ __forceinline__ void mma_tf32(float c[4],
                                         uint32_t a0, uint32_t a1, uint32_t a2, uint32_t a3,
                                         uint32_t b0, uint32_t b1) {
    asm volatile(
        "mma.sync.aligned.m16n8k8.row.col.f32.tf32.tf32.f32 "
        "{%0,%1,%2,%3}, {%4,%5,%6,%7}, {%8,%9}, {%0,%1,%2,%3};"
        : "+f"(c[0]), "+f"(c[1]), "+f"(c[2]), "+f"(c[3])
        : "r"(a0), "r"(a1), "r"(a2), "r"(a3), "r"(b0), "r"(b1));
}

// ---------------- fast exp on the FFMA pipe ---------------------------------
__device__ __forceinline__ float fexp(float x) {
    float y = fmaxf(x * 1.4426950408889634f, -126.0f);
    float n = rintf(y);
    float f = y - n;
    float p =              1.5403530393381606e-4f;
    p = fmaf(p, f, 1.3333558146428443e-3f);
    p = fmaf(p, f, 9.6181291076284772e-3f);
    p = fmaf(p, f, 5.5504108664821580e-2f);
    p = fmaf(p, f, 2.4022650695910071e-1f);
    p = fmaf(p, f, 6.9314718055994531e-1f);
    p = fmaf(p, f, 1.0f);
    int e = (((int)n) + 127) << 23;
    return p * __int_as_float(e);
}

// ============================================================================
// K1: tf32 mma.sync GEMM  C = X @ W^T + b   (M=4096, N=1024, K=1024)
// CTA 128x128, BK=32, 256 threads = 8 warps in 2(m) x 4(n), warp tile 64x32.
// smem stride 36 floats => 16B-aligned rows, conflict-free fragment loads.
// ============================================================================
#define BK 32
#define ASTR 36

__global__ void __launch_bounds__(256)
gemm_tf32(const float* __restrict__ A, const float* __restrict__ W,
          const float* __restrict__ bias, int which) {
    float* C = (which == 0) ? g_Q : (which == 1) ? g_K : g_V;
    __shared__ uint32_t sA[128 * ASTR];   // [m][k] tf32
    __shared__ uint32_t sB[128 * ASTR];   // [n][k] tf32

    const int tid  = threadIdx.x;
    const int wid  = tid >> 5;
    const int lane = tid & 31;
    const int grp  = lane >> 2;       // 0..7
    const int qid  = lane & 3;        // 0..3
    const int m0 = blockIdx.y * 128;
    const int n0 = blockIdx.x * 128;
    const int warp_m = (wid & 1) * 64;        // 0 or 64
    const int warp_n = (wid >> 1) * 32;       // 0,32,64,96

    float acc[4][4][4];               // [mt][nt][c0..c3]
#pragma unroll
    for (int mt = 0; mt < 4; mt++)
#pragma unroll
        for (int nt = 0; nt < 4; nt++)
#pragma unroll
            for (int r = 0; r < 4; r++) acc[mt][nt][r] = 0.f;

    for (int k0 = 0; k0 < DD; k0 += BK) {
        // load + convert: A tile [128][32], B tile (=W rows) [128][32]
#pragma unroll
        for (int t = 0; t < 4; t++) {
            int idx = tid + t * 256;          // 0..1023
            int row = idx >> 3;               // 0..127
            int c4  = idx & 7;                // 0..7
            float4 va = *(const float4*)(A + (size_t)(m0 + row) * DD + k0 + c4 * 4);
            uint4 ua = make_uint4(f2tf32(va.x), f2tf32(va.y), f2tf32(va.z), f2tf32(va.w));
            *(uint4*)(sA + row * ASTR + c4 * 4) = ua;
            float4 vb = *(const float4*)(W + (size_t)(n0 + row) * DD + k0 + c4 * 4);
            uint4 ub = make_uint4(f2tf32(vb.x), f2tf32(vb.y), f2tf32(vb.z), f2tf32(vb.w));
            *(uint4*)(sB + row * ASTR + c4 * 4) = ub;
        }
        __syncthreads();

#pragma unroll
        for (int ks = 0; ks < BK / 8; ks++) {
            const int kk = ks * 8;
            uint32_t af[4][4], bf[4][2];
#pragma unroll
            for (int mt = 0; mt < 4; mt++) {
                const uint32_t* ap = sA + (warp_m + mt * 16 + grp) * ASTR + kk + qid;
                af[mt][0] = ap[0];
                af[mt][1] = ap[8 * ASTR];
                af[mt][2] = ap[4];
                af[mt][3] = ap[8 * ASTR + 4];
            }
#pragma unroll
            for (int nt = 0; nt < 4; nt++) {
                const uint32_t* bp = sB + (warp_n + nt * 8 + grp) * ASTR + kk + qid;
                bf[nt][0] = bp[0];
                bf[nt][1] = bp[4];
            }
#pragma unroll
            for (int mt = 0; mt < 4; mt++)
#pragma unroll
                for (int nt = 0; nt < 4; nt++)
                    mma_tf32(acc[mt][nt], af[mt][0], af[mt][1], af[mt][2], af[mt][3],
                             bf[nt][0], bf[nt][1]);
        }
        __syncthreads();
    }

    // epilogue: c0,c1 -> (row grp, col 2q,2q+1); c2,c3 -> row grp+8
#pragma unroll
    for (int mt = 0; mt < 4; mt++) {
#pragma unroll
        for (int nt = 0; nt < 4; nt++) {
            int col = n0 + warp_n + nt * 8 + 2 * qid;
            float bx = bias[col], by = bias[col + 1];
            int r0 = m0 + warp_m + mt * 16 + grp;
            float2 o0 = make_float2(acc[mt][nt][0] + bx, acc[mt][nt][1] + by);
            *(float2*)(C + (size_t)r0 * DD + col) = o0;
            float2 o1 = make_float2(acc[mt][nt][2] + bx, acc[mt][nt][3] + by);
            *(float2*)(C + (size_t)(r0 + 8) * DD + col) = o1;
        }
    }
}

// ============================================================================
// K2: scores pass — e = exp(s/8), cache in g_S, row sums Z1 in g_Z
// ============================================================================
#define QSTR 68

__global__ void __launch_bounds__(256)
attn_scores() {
    __shared__ float Qs[64 * QSTR];
    __shared__ float Ks[64 * QSTR];
    const int bh = blockIdx.z;
    const int b  = bh >> 4, h = bh & 15;
    const int q0 = blockIdx.x * 64;
    const int tid = threadIdx.x;
    const int ty = tid >> 4, tx = tid & 15;
    float* Sm = g_S + (size_t)bh * SS * SS;

    // load Q transposed: Qs[w][q]
#pragma unroll
    for (int r = 0; r < 4; r++) {
        int idx = tid + r * 256;
        int row = idx >> 4;
        int c4  = idx & 15;
        float4 v = *(const float4*)(g_Q + (size_t)(b*SS + q0 + row) * DD + h*HW + c4*4);
        Qs[(c4*4+0)*QSTR + row] = v.x; Qs[(c4*4+1)*QSTR + row] = v.y;
        Qs[(c4*4+2)*QSTR + row] = v.z; Qs[(c4*4+3)*QSTR + row] = v.w;
    }

    float z[4] = {0.f, 0.f, 0.f, 0.f};

    for (int n0 = 0; n0 < SS; n0 += 64) {
#pragma unroll
        for (int r = 0; r < 4; r++) {
            int idx = tid + r * 256;
            int row = idx >> 4;
            int c4  = idx & 15;
            float4 v = *(const float4*)(g_K + (size_t)(b*SS + n0 + row) * DD + h*HW + c4*4);
            Ks[(c4*4+0)*QSTR + row] = v.x; Ks[(c4*4+1)*QSTR + row] = v.y;
            Ks[(c4*4+2)*QSTR + row] = v.z; Ks[(c4*4+3)*QSTR + row] = v.w;
        }
        __syncthreads();

        float s[4][4];
#pragma unroll
        for (int i = 0; i < 4; i++)
#pragma unroll
            for (int j = 0; j < 4; j++) s[i][j] = 0.f;
#pragma unroll
        for (int w = 0; w < 64; w++) {
            float4 a4 = *(const float4*)(Qs + w*QSTR + ty*4);
            float4 b4 = *(const float4*)(Ks + w*QSTR + tx*4);
            float a[4] = {a4.x, a4.y, a4.z, a4.w};
            float bb[4] = {b4.x, b4.y, b4.z, b4.w};
#pragma unroll
            for (int i = 0; i < 4; i++)
#pragma unroll
                for (int j = 0; j < 4; j++) s[i][j] = fmaf(a[i], bb[j], s[i][j]);
        }
#pragma unroll
        for (int i = 0; i < 4; i++) {
#pragma unroll
            for (int j = 0; j < 4; j++) {
                float e = fexp(fminf(s[i][j] * 0.125f, 30.f));
                z[i] += e;
                s[i][j] = e;
            }
            *(float4*)(Sm + (size_t)(q0 + ty*4 + i) * SS + n0 + tx*4) =
                make_float4(s[i][0], s[i][1], s[i][2], s[i][3]);
        }
        __syncthreads();
    }

    // reduce z over the 16 tx lanes (same ty)
#pragma unroll
    for (int o = 8; o; o >>= 1)
#pragma unroll
        for (int i = 0; i < 4; i++) z[i] += __shfl_xor_sync(0xffffffffu, z[i], o);
    if (tx == 0)
        *(float4*)(g_Z + (size_t)bh * SS + q0 + ty*4) = make_float4(z[0], z[1], z[2], z[3]);
}

// ============================================================================
// K3: transform + PV — t = exp(e/Z1); out = (t @ V) / Z2
// Ts stored transposed [k][q] so PV does LDS.128 on both operands.
// ============================================================================
#define TSTR2 68

__global__ void __launch_bounds__(256)
attn_pv(float* __restrict__ out) {
    __shared__ float Ts[64 * TSTR2];   // [k][q]
    __shared__ float Vs[64 * TSTR2];   // [k][w]
    const int bh = blockIdx.z;
    const int b  = bh >> 4, h = bh & 15;
    const int q0 = blockIdx.x * 64;
    const int tid = threadIdx.x;
    const int ty = tid >> 4, tx = tid & 15;
    const float* Sm = g_S + (size_t)bh * SS * SS;

    float4 zv = *(const float4*)(g_Z + (size_t)bh * SS + q0 + ty*4);
    float invZ[4] = {1.f/zv.x, 1.f/zv.y, 1.f/zv.z, 1.f/zv.w};

    float acc[4][4];
    float z2[4] = {0.f, 0.f, 0.f, 0.f};
#pragma unroll
    for (int i = 0; i < 4; i++)
#pragma unroll
        for (int j = 0; j < 4; j++) acc[i][j] = 0.f;

    for (int n0 = 0; n0 < SS; n0 += 64) {
        // V tile: Vs[k][w]
#pragma unroll
        for (int r = 0; r < 4; r++) {
            int idx = tid + r * 256;
            int row = idx >> 4;
            int c4  = idx & 15;
            float4 v = *(const float4*)(g_V + (size_t)(b*SS + n0 + row) * DD + h*HW + c4*4);
            *(float4*)(Vs + row*TSTR2 + c4*4) = v;
        }
        // E tile -> t, z2, transposed smem store
        float4 tv[4];
#pragma unroll
        for (int i = 0; i < 4; i++) {
            float4 e = *(const float4*)(Sm + (size_t)(q0 + ty*4 + i) * SS + n0 + tx*4);
            float4 t;
            t.x = fexp(e.x * invZ[i]); t.y = fexp(e.y * invZ[i]);
            t.z = fexp(e.z * invZ[i]); t.w = fexp(e.w * invZ[i]);
            z2[i] += (t.x + t.y) + (t.z + t.w);
            tv[i] = t;
        }
        {
            float* tp = Ts + (tx*4)*TSTR2 + ty*4;
            *(float4*)(tp)             = make_float4(tv[0].x, tv[1].x, tv[2].x, tv[3].x);
            *(float4*)(tp + TSTR2)     = make_float4(tv[0].y, tv[1].y, tv[2].y, tv[3].y);
            *(float4*)(tp + 2*TSTR2)   = make_float4(tv[0].z, tv[1].z, tv[2].z, tv[3].z);
            *(float4*)(tp + 3*TSTR2)   = make_float4(tv[0].w, tv[1].w, tv[2].w, tv[3].w);
        }
        __syncthreads();

#pragma unroll
        for (int k = 0; k < 64; k++) {
            float4 ta = *(const float4*)(Ts + k*TSTR2 + ty*4);
            float4 vv = *(const float4*)(Vs + k*TSTR2 + tx*4);
            float a[4] = {ta.x, ta.y, ta.z, ta.w};
#pragma unroll
            for (int i = 0; i < 4; i++) {
                acc[i][0] = fmaf(a[i], vv.x, acc[i][0]);
                acc[i][1] = fmaf(a[i], vv.y, acc[i][1]);
                acc[i][2] = fmaf(a[i], vv.z, acc[i][2]);
                acc[i][3] = fmaf(a[i], vv.w, acc[i][3]);
            }
        }
        __syncthreads();
    }

#pragma unroll
    for (int o = 8; o; o >>= 1)
#pragma unroll
        for (int i = 0; i < 4; i++) z2[i] += __shfl_xor_sync(0xffffffffu, z2[i], o);

#pragma unroll
    for (int i = 0; i < 4; i++) {
        float r = 1.0f / z2[i];
        float4 o;
        o.x = acc[i][0] * r; o.y = acc[i][1] * r;
        o.z = acc[i][2] * r; o.w = acc[i][3] * r;
        *(float4*)(out + (size_t)(b*SS + q0 + ty*4 + i) * DD + h*HW + tx*4) = o;
    }
}

// ---------------- launch -----------------------------------------------------
extern "C" void kernel_launch(void* const* d_in, const int* in_sizes, int n_in,
                              void* d_out, int out_size) {
    const float* x  = (const float*)d_in[0];
    const float* Wq = (const float*)d_in[1];
    const float* bq = (const float*)d_in[2];
    const float* Wk = (const float*)d_in[3];
    const float* bk = (const float*)d_in[4];
    const float* Wv = (const float*)d_in[5];
    const float* bv = (const float*)d_in[6];
    float* out = (float*)d_out;

    dim3 gproj(DD / 128, MM / 128);             // (8, 32)
    gemm_tf32<<<gproj, 256>>>(x, Wq, bq, 0);
    gemm_tf32<<<gproj, 256>>>(x, Wk, bk, 1);
    gemm_tf32<<<gproj, 256>>>(x, Wv, bv, 2);

    dim3 gs(SS / 64, 1, BB * HH);               // (32, 1, 32)
    attn_scores<<<gs, 256>>>();
    attn_pv<<<gs, 256>>>(out);
}

// round 6
// speedup vs baseline: 3.1989x; 2.1689x over previous
#include <cuda_runtime.h>
#include <cstdint>
#include <math.h>

#define BB 2
#define SS 2048
#define DD 1024
#define HH 16
#define HW 64
#define MM (BB*SS)   // 4096

// ---------------- scratch (no cudaMalloc allowed) ---------------------------
__device__ float g_Q[(size_t)MM * DD];                 // 16 MB
__device__ float g_K[(size_t)MM * DD];                 // 16 MB
__device__ float g_V[(size_t)MM * DD];                 // 16 MB
__device__ float g_S[(size_t)BB * HH * SS * SS];       // 512 MB  (e^s cache)
__device__ float g_Z[(size_t)BB * HH * SS];            // row sums Z1

// ---------------- tf32 helpers (non-arch-specific PTX only) -----------------
__device__ __forceinline__ uint32_t f2tf32(float x) {
    uint32_t u; asm("cvt.rna.tf32.f32 %0, %1;" : "=r"(u) : "f"(x)); return u;
}

__device__ __forceinline__ void mma_tf32(float c[4],
                                         uint32_t a0, uint32_t a1, uint32_t a2, uint32_t a3,
                                         uint32_t b0, uint32_t b1) {
    asm volatile(
        "mma.sync.aligned.m16n8k8.row.col.f32.tf32.tf32.f32 "
        "{%0,%1,%2,%3}, {%4,%5,%6,%7}, {%8,%9}, {%0,%1,%2,%3};"
        : "+f"(c[0]), "+f"(c[1]), "+f"(c[2]), "+f"(c[3])
        : "r"(a0), "r"(a1), "r"(a2), "r"(a3), "r"(b0), "r"(b1));
}

// ---------------- fast exp on the FFMA pipe ---------------------------------
__device__ __forceinline__ float fexp(float x) {
    float y = fmaxf(x * 1.4426950408889634f, -126.0f);
    float n = rintf(y);
    float f = y - n;
    float p =              1.5403530393381606e-4f;
    p = fmaf(p, f, 1.3333558146428443e-3f);
    p = fmaf(p, f, 9.6181291076284772e-3f);
    p = fmaf(p, f, 5.5504108664821580e-2f);
    p = fmaf(p, f, 2.4022650695910071e-1f);
    p = fmaf(p, f, 6.9314718055994531e-1f);
    p = fmaf(p, f, 1.0f);
    int e = (((int)n) + 127) << 23;
    return p * __int_as_float(e);
}

// ============================================================================
// K1: tf32 mma.sync GEMM  C = X @ W^T + b   (unchanged from R5, passing)
// ============================================================================
#define BK 32
#define ASTR 36

__global__ void __launch_bounds__(256)
gemm_tf32(const float* __restrict__ A, const float* __restrict__ W,
          const float* __restrict__ bias, int which) {
    float* C = (which == 0) ? g_Q : (which == 1) ? g_K : g_V;
    __shared__ uint32_t sA[128 * ASTR];
    __shared__ uint32_t sB[128 * ASTR];

    const int tid  = threadIdx.x;
    const int wid  = tid >> 5;
    const int lane = tid & 31;
    const int grp  = lane >> 2;
    const int qid  = lane & 3;
    const int m0 = blockIdx.y * 128;
    const int n0 = blockIdx.x * 128;
    const int warp_m = (wid & 1) * 64;
    const int warp_n = (wid >> 1) * 32;

    float acc[4][4][4];
#pragma unroll
    for (int mt = 0; mt < 4; mt++)
#pragma unroll
        for (int nt = 0; nt < 4; nt++)
#pragma unroll
            for (int r = 0; r < 4; r++) acc[mt][nt][r] = 0.f;

    for (int k0 = 0; k0 < DD; k0 += BK) {
#pragma unroll
        for (int t = 0; t < 4; t++) {
            int idx = tid + t * 256;
            int row = idx >> 3;
            int c4  = idx & 7;
            float4 va = *(const float4*)(A + (size_t)(m0 + row) * DD + k0 + c4 * 4);
            *(uint4*)(sA + row * ASTR + c4 * 4) =
                make_uint4(f2tf32(va.x), f2tf32(va.y), f2tf32(va.z), f2tf32(va.w));
            float4 vb = *(const float4*)(W + (size_t)(n0 + row) * DD + k0 + c4 * 4);
            *(uint4*)(sB + row * ASTR + c4 * 4) =
                make_uint4(f2tf32(vb.x), f2tf32(vb.y), f2tf32(vb.z), f2tf32(vb.w));
        }
        __syncthreads();

#pragma unroll
        for (int ks = 0; ks < BK / 8; ks++) {
            const int kk = ks * 8;
            uint32_t af[4][4], bf[4][2];
#pragma unroll
            for (int mt = 0; mt < 4; mt++) {
                const uint32_t* ap = sA + (warp_m + mt * 16 + grp) * ASTR + kk + qid;
                af[mt][0] = ap[0];
                af[mt][1] = ap[8 * ASTR];
                af[mt][2] = ap[4];
                af[mt][3] = ap[8 * ASTR + 4];
            }
#pragma unroll
            for (int nt = 0; nt < 4; nt++) {
                const uint32_t* bp = sB + (warp_n + nt * 8 + grp) * ASTR + kk + qid;
                bf[nt][0] = bp[0];
                bf[nt][1] = bp[4];
            }
#pragma unroll
            for (int mt = 0; mt < 4; mt++)
#pragma unroll
                for (int nt = 0; nt < 4; nt++)
                    mma_tf32(acc[mt][nt], af[mt][0], af[mt][1], af[mt][2], af[mt][3],
                             bf[nt][0], bf[nt][1]);
        }
        __syncthreads();
    }

#pragma unroll
    for (int mt = 0; mt < 4; mt++) {
#pragma unroll
        for (int nt = 0; nt < 4; nt++) {
            int col = n0 + warp_n + nt * 8 + 2 * qid;
            float bx = bias[col], by = bias[col + 1];
            int r0 = m0 + warp_m + mt * 16 + grp;
            *(float2*)(C + (size_t)r0 * DD + col) =
                make_float2(acc[mt][nt][0] + bx, acc[mt][nt][1] + by);
            *(float2*)(C + (size_t)(r0 + 8) * DD + col) =
                make_float2(acc[mt][nt][2] + bx, acc[mt][nt][3] + by);
        }
    }
}

// ============================================================================
// K2: tf32 mma.sync scores — e = exp(s/8) -> g_S, Z1 -> g_Z
// CTA: 128 q rows x full n loop (128 per tile). 8 warps (2m x 4n), warp 64x32.
// ============================================================================
#define SSTR 68

__global__ void __launch_bounds__(256)
attn_scores_mma() {
    extern __shared__ uint32_t dsm[];
    uint32_t* Qs = dsm;                 // [128][SSTR] tf32
    uint32_t* Ks = dsm + 128 * SSTR;    // [128][SSTR] tf32
    __shared__ float sz[4][128];

    const int bh = blockIdx.y;
    const int b  = bh >> 4, h = bh & 15;
    const int q0 = blockIdx.x * 128;
    const int tid  = threadIdx.x;
    const int wid  = tid >> 5;
    const int lane = tid & 31;
    const int grp  = lane >> 2;
    const int qid  = lane & 3;
    const int widm = wid & 1, widn = wid >> 1;
    const int warp_m = widm * 64, warp_n = widn * 32;
    float* Sm = g_S + (size_t)bh * SS * SS;

    // Q tile [128][64] -> tf32 smem (once)
#pragma unroll
    for (int t = 0; t < 8; t++) {
        int idx = tid + t * 256;
        int row = idx >> 4;
        int c4  = idx & 15;
        float4 v = *(const float4*)(g_Q + (size_t)(b*SS + q0 + row) * DD + h*HW + c4*4);
        *(uint4*)(Qs + row * SSTR + c4 * 4) =
            make_uint4(f2tf32(v.x), f2tf32(v.y), f2tf32(v.z), f2tf32(v.w));
    }

    float zlo[4] = {0.f,0.f,0.f,0.f}, zhi[4] = {0.f,0.f,0.f,0.f};

    for (int n0 = 0; n0 < SS; n0 += 128) {
        __syncthreads();
#pragma unroll
        for (int t = 0; t < 8; t++) {
            int idx = tid + t * 256;
            int row = idx >> 4;
            int c4  = idx & 15;
            float4 v = *(const float4*)(g_K + (size_t)(b*SS + n0 + row) * DD + h*HW + c4*4);
            *(uint4*)(Ks + row * SSTR + c4 * 4) =
                make_uint4(f2tf32(v.x), f2tf32(v.y), f2tf32(v.z), f2tf32(v.w));
        }
        __syncthreads();

        float acc[4][4][4];
#pragma unroll
        for (int mt = 0; mt < 4; mt++)
#pragma unroll
            for (int nt = 0; nt < 4; nt++)
#pragma unroll
                for (int r = 0; r < 4; r++) acc[mt][nt][r] = 0.f;

#pragma unroll
        for (int ks = 0; ks < 8; ks++) {
            const int kk = ks * 8;
            uint32_t af[4][4], bf[4][2];
#pragma unroll
            for (int mt = 0; mt < 4; mt++) {
                const uint32_t* ap = Qs + (warp_m + mt * 16 + grp) * SSTR + kk + qid;
                af[mt][0] = ap[0];
                af[mt][1] = ap[8 * SSTR];
                af[mt][2] = ap[4];
                af[mt][3] = ap[8 * SSTR + 4];
            }
#pragma unroll
            for (int nt = 0; nt < 4; nt++) {
                const uint32_t* bp = Ks + (warp_n + nt * 8 + grp) * SSTR + kk + qid;
                bf[nt][0] = bp[0];
                bf[nt][1] = bp[4];
            }
#pragma unroll
            for (int mt = 0; mt < 4; mt++)
#pragma unroll
                for (int nt = 0; nt < 4; nt++)
                    mma_tf32(acc[mt][nt], af[mt][0], af[mt][1], af[mt][2], af[mt][3],
                             bf[nt][0], bf[nt][1]);
        }

        // transform + store e, accumulate z
#pragma unroll
        for (int mt = 0; mt < 4; mt++) {
            int r1 = warp_m + mt * 16 + grp;
            int r2 = r1 + 8;
#pragma unroll
            for (int nt = 0; nt < 4; nt++) {
                int col = n0 + warp_n + nt * 8 + 2 * qid;
                float e0 = fexp(fminf(acc[mt][nt][0] * 0.125f, 30.f));
                float e1 = fexp(fminf(acc[mt][nt][1] * 0.125f, 30.f));
                float e2 = fexp(fminf(acc[mt][nt][2] * 0.125f, 30.f));
                float e3 = fexp(fminf(acc[mt][nt][3] * 0.125f, 30.f));
                zlo[mt] += e0 + e1;
                zhi[mt] += e2 + e3;
                *(float2*)(Sm + (size_t)(q0 + r1) * SS + col) = make_float2(e0, e1);
                *(float2*)(Sm + (size_t)(q0 + r2) * SS + col) = make_float2(e2, e3);
            }
        }
    }

    // reduce z over the 4 qid lanes (butterfly: all lanes get the sum)
#pragma unroll
    for (int o = 1; o <= 2; o <<= 1)
#pragma unroll
        for (int mt = 0; mt < 4; mt++) {
            zlo[mt] += __shfl_xor_sync(0xffffffffu, zlo[mt], o);
            zhi[mt] += __shfl_xor_sync(0xffffffffu, zhi[mt], o);
        }
    if (qid == 0) {
#pragma unroll
        for (int mt = 0; mt < 4; mt++) {
            sz[widn][warp_m + mt * 16 + grp]     = zlo[mt];
            sz[widn][warp_m + mt * 16 + grp + 8] = zhi[mt];
        }
    }
    __syncthreads();
    if (tid < 128) {
        float z = (sz[0][tid] + sz[1][tid]) + (sz[2][tid] + sz[3][tid]);
        g_Z[(size_t)bh * SS + q0 + tid] = z;
    }
}

// ============================================================================
// K3: tf32 mma.sync PV — t = exp(e/Z1); out = (t @ V)/Z2
// CTA: 128 q x 64 w; 8 warps all-m (16 q each), k-loop step 64.
// t computed in-register from staged e tile -> A fragments directly.
// ============================================================================
#define ESTR 68
#define VSTR 72

__global__ void __launch_bounds__(256)
attn_pv_mma(float* __restrict__ out) {
    extern __shared__ float dsm2[];
    float*    Es = dsm2;                          // [128][ESTR] fp32
    uint32_t* Vs = (uint32_t*)(dsm2 + 128 * ESTR); // [64][VSTR] tf32

    const int bh = blockIdx.y;
    const int b  = bh >> 4, h = bh & 15;
    const int q0 = blockIdx.x * 128;
    const int tid  = threadIdx.x;
    const int wid  = tid >> 5;
    const int lane = tid & 31;
    const int grp  = lane >> 2;
    const int qid  = lane & 3;
    const float* Sm = g_S + (size_t)bh * SS * SS;

    const int r1 = wid * 16 + grp;      // warp-local q rows
    const int r2 = r1 + 8;
    const float invZlo = 1.0f / g_Z[(size_t)bh * SS + q0 + r1];
    const float invZhi = 1.0f / g_Z[(size_t)bh * SS + q0 + r2];

    float acc[8][4];
#pragma unroll
    for (int nt = 0; nt < 8; nt++)
#pragma unroll
        for (int r = 0; r < 4; r++) acc[nt][r] = 0.f;
    float z2lo = 0.f, z2hi = 0.f;

    for (int k0 = 0; k0 < SS; k0 += 64) {
        __syncthreads();
        // e tile [128][64] fp32
#pragma unroll
        for (int t = 0; t < 8; t++) {
            int idx = tid + t * 256;
            int row = idx >> 4;
            int c4  = idx & 15;
            float4 v = *(const float4*)(Sm + (size_t)(q0 + row) * SS + k0 + c4*4);
            *(float4*)(Es + row * ESTR + c4 * 4) = v;
        }
        // V tile [64][64] tf32
#pragma unroll
        for (int t = 0; t < 4; t++) {
            int idx = tid + t * 256;
            int row = idx >> 4;
            int c4  = idx & 15;
            float4 v = *(const float4*)(g_V + (size_t)(b*SS + k0 + row) * DD + h*HW + c4*4);
            *(uint4*)(Vs + row * VSTR + c4 * 4) =
                make_uint4(f2tf32(v.x), f2tf32(v.y), f2tf32(v.z), f2tf32(v.w));
        }
        __syncthreads();

#pragma unroll
        for (int ks = 0; ks < 8; ks++) {
            const int kk = ks * 8;
            const float* ep  = Es + r1 * ESTR + kk + qid;
            const float* ep2 = Es + r2 * ESTR + kk + qid;
            float t0 = fexp(ep[0]  * invZlo);
            float t1 = fexp(ep2[0] * invZhi);
            float t2 = fexp(ep[4]  * invZlo);
            float t3 = fexp(ep2[4] * invZhi);
            z2lo += t0 + t2;
            z2hi += t1 + t3;
            uint32_t a0 = f2tf32(t0), a1 = f2tf32(t1), a2 = f2tf32(t2), a3 = f2tf32(t3);
#pragma unroll
            for (int nt = 0; nt < 8; nt++) {
                const uint32_t* bp = Vs + (kk + qid) * VSTR + nt * 8 + grp;
                mma_tf32(acc[nt], a0, a1, a2, a3, bp[0], bp[4 * VSTR]);
            }
        }
    }

    // Z2 butterfly over qid lanes (all lanes receive the total)
#pragma unroll
    for (int o = 1; o <= 2; o <<= 1) {
        z2lo += __shfl_xor_sync(0xffffffffu, z2lo, o);
        z2hi += __shfl_xor_sync(0xffffffffu, z2hi, o);
    }
    const float rlo = 1.0f / z2lo;
    const float rhi = 1.0f / z2hi;

#pragma unroll
    for (int nt = 0; nt < 8; nt++) {
        int col = h * HW + nt * 8 + 2 * qid;
        *(float2*)(out + (size_t)(b*SS + q0 + r1) * DD + col) =
            make_float2(acc[nt][0] * rlo, acc[nt][1] * rlo);
        *(float2*)(out + (size_t)(b*SS + q0 + r2) * DD + col) =
            make_float2(acc[nt][2] * rhi, acc[nt][3] * rhi);
    }
}

// ---------------- launch -----------------------------------------------------
extern "C" void kernel_launch(void* const* d_in, const int* in_sizes, int n_in,
                              void* d_out, int out_size) {
    const float* x  = (const float*)d_in[0];
    const float* Wq = (const float*)d_in[1];
    const float* bq = (const float*)d_in[2];
    const float* Wk = (const float*)d_in[3];
    const float* bk = (const float*)d_in[4];
    const float* Wv = (const float*)d_in[5];
    const float* bv = (const float*)d_in[6];
    float* out = (float*)d_out;

    dim3 gproj(DD / 128, MM / 128);             // (8, 32)
    gemm_tf32<<<gproj, 256>>>(x, Wq, bq, 0);
    gemm_tf32<<<gproj, 256>>>(x, Wk, bk, 1);
    gemm_tf32<<<gproj, 256>>>(x, Wv, bv, 2);

    const int smem_sc = 2 * 128 * SSTR * sizeof(uint32_t);          // 69632
    const int smem_pv = (128 * ESTR + 64 * VSTR) * sizeof(float);   // 53248
    cudaFuncSetAttribute(attn_scores_mma,
                         cudaFuncAttributeMaxDynamicSharedMemorySize, smem_sc);
    cudaFuncSetAttribute(attn_pv_mma,
                         cudaFuncAttributeMaxDynamicSharedMemorySize, smem_pv);

    dim3 gs(SS / 128, BB * HH);                 // (16, 32)
    attn_scores_mma<<<gs, 256, smem_sc>>>();
    attn_pv_mma<<<gs, 256, smem_pv>>>(out);
}